// round 9
// baseline (speedup 1.0000x reference)
#include <cuda_runtime.h>
#include <cstdint>

#define BV     32
#define TT     2048
#define DD     512
#define MAXRUN 1024
#define GBLK   608                 // 152 SMs * 4
#define MAXU   (BV * 128)         // max units: ceil(1024 quals / 8) per video
#define CTf    0.7f
#define CPTf   0.5f

// ---------------- device scratch (no allocations allowed) ----------------
// g_rows[b*2048 + i] : {t | endflag<<31, coeff bits} for qual-run rows, t-ordered
// g_chunkoff[b*258 + j] : row offset of qual run 4*j (clamped to total rows)
// g_units : compact list of active units (b<<8 | c), c = 8-run chunk index
// g_usum[b*128 + c] : per-unit feat sum (fixed slot -> deterministic output)
__device__ int2  g_rows[BV * TT];
__device__ int   g_chunkoff[BV * 258];
__device__ int   g_units[MAXU];
__device__ float g_usum[MAXU];
__device__ float g_vid_attn[BV];
__device__ int   g_nqual[BV];
__device__ int   g_ucount;
__device__ int   g_ready;
__device__ int   g_qhead;
__device__ int   g_done;

__global__ __launch_bounds__(256, 4)
void fusedKernel(const float* __restrict__ attn,
                 const float* __restrict__ feat,
                 float* __restrict__ out)
{
    __shared__ float         s_attn[TT];          // 8 KB
    __shared__ unsigned char s_predB[256];
    __shared__ unsigned char s_repB[256];
    __shared__ unsigned int  s_word[64];
    __shared__ unsigned int  s_repW[64];
    __shared__ int           s_scnt[64];
    __shared__ int           s_wbase[64];
    __shared__ int           s_total;
    __shared__ int           s_rstart[MAXRUN];
    __shared__ int           s_rlen[MAXRUN];
    __shared__ float         s_rmse[MAXRUN];
    __shared__ float         s_ric[MAXRUN];
    __shared__ float         s_rir[MAXRUN];
    __shared__ int           s_wq[8], s_wr[8];
    __shared__ float         s_red[8];
    __shared__ float         s_part[8];
    __shared__ int           s_nq, s_trows, s_ubase, s_nch8;
    __shared__ int           s_u, s_nunits, s_isLast;

    const int tid  = threadIdx.x;
    const int lane = tid & 31;
    const int warp = tid >> 5;

    // ====================== phase 1: per-video analysis ======================
    if (blockIdx.x < BV) {
        const int b = blockIdx.x;
        const float* a_row = attn + (b << 11);

        const float4 v0 = ((const float4*)a_row)[tid * 2];
        const float4 v1 = ((const float4*)a_row)[tid * 2 + 1];
        ((float4*)s_attn)[tid * 2]     = v0;
        ((float4*)s_attn)[tid * 2 + 1] = v1;
        const float av[8] = {v0.x, v0.y, v0.z, v0.w, v1.x, v1.y, v1.z, v1.w};
        unsigned int pb = 0, rb8 = 0;
        #pragma unroll
        for (int j = 0; j < 8; j++) {
            pb  |= (av[j] > CPTf ? 1u : 0u) << j;
            rb8 |= (av[j] > CTf  ? 1u : 0u) << j;
        }
        s_predB[tid] = (unsigned char)pb;
        s_repB[tid]  = (unsigned char)rb8;
        __syncthreads();

        unsigned int myStart = 0, myWord = 0;
        if (tid < 64) {
            myWord = (unsigned)s_predB[4*tid]
                   | ((unsigned)s_predB[4*tid+1] << 8)
                   | ((unsigned)s_predB[4*tid+2] << 16)
                   | ((unsigned)s_predB[4*tid+3] << 24);
            s_repW[tid] = (unsigned)s_repB[4*tid]
                        | ((unsigned)s_repB[4*tid+1] << 8)
                        | ((unsigned)s_repB[4*tid+2] << 16)
                        | ((unsigned)s_repB[4*tid+3] << 24);
            const unsigned carry = tid ? ((s_predB[4*tid - 1] >> 7) & 1u) : 0u;
            myStart = myWord & ~((myWord << 1) | carry);
            s_word[tid] = myWord;
            s_scnt[tid] = __popc(myStart);
        }
        __syncthreads();

        if (warp == 0) {                       // scan 64 word start-counts
            const int c0 = s_scnt[2*lane], c1 = s_scnt[2*lane+1];
            int incl = c0 + c1;
            #pragma unroll
            for (int o = 1; o < 32; o <<= 1) {
                int u = __shfl_up_sync(0xffffffffu, incl, o);
                if (lane >= o) incl += u;
            }
            const int excl = incl - (c0 + c1);
            s_wbase[2*lane]     = excl;
            s_wbase[2*lane + 1] = excl + c0;
            if (lane == 31) s_total = incl;
        }
        __syncthreads();

        // ---- run extraction: bit-parallel, no atomics ----
        if (tid < 64 && myStart) {
            int rbase = s_wbase[tid];
            unsigned sb = myStart;
            while (sb) {
                const int bit = __ffs(sb) - 1; sb &= sb - 1;
                const int t0 = tid * 32 + bit;
                int len = 0, ww = tid;
                unsigned cur = myWord >> bit;
                int avail = 32 - bit;
                while (true) {
                    const unsigned inv = ~cur;
                    int c = inv ? (__ffs(inv) - 1) : 32;
                    if (c > avail) c = avail;
                    len += c;
                    if (c < avail) break;
                    if (++ww >= 64) break;
                    cur = s_word[ww]; avail = 32;
                }
                float sum = 0.f; int rep = 0;
                for (int j = 0; j < len; j++) {
                    const float a = s_attn[t0 + j];
                    sum += a; rep += (a > CTf) ? 1 : 0;
                }
                const float mean = sum / (float)len;
                float ssq = 0.f;
                for (int j = 0; j < len; j++) {
                    const float d = s_attn[t0 + j] - mean;
                    ssq += d * d;
                }
                s_rstart[rbase] = t0;
                s_rlen[rbase]   = len;
                s_rmse[rbase]   = ssq / (float)len;
                s_ric[rbase]    = 1.0f / (float)len;
                s_rir[rbase]    = (rep > 0) ? (1.0f / (float)rep) : 0.0f;
                rbase++;
            }
        }
        __syncthreads();

        // ---- compact qual runs, emit row list + chunk offsets + unit list ----
        const int total = s_total;
        float attnAcc = 0.f;
        int t0l[4], Ll[4]; float icl[4], irl[4];
        int nloc = 0, q = 0, rl = 0;
        #pragma unroll
        for (int j = 0; j < 4; j++) {
            const int r = 4*tid + j;
            if (r < total) {
                attnAcc += s_rmse[r];
                const float ir = s_rir[r];
                if (ir != 0.f) {
                    t0l[nloc] = s_rstart[r]; Ll[nloc] = s_rlen[r];
                    icl[nloc] = s_ric[r];    irl[nloc] = ir;
                    nloc++; q++; rl += s_rlen[r];
                }
            }
        }
        int qi = q, rli = rl;
        #pragma unroll
        for (int o = 1; o < 32; o <<= 1) {
            int u1 = __shfl_up_sync(0xffffffffu, qi,  o);
            int u2 = __shfl_up_sync(0xffffffffu, rli, o);
            if (lane >= o) { qi += u1; rli += u2; }
        }
        if (lane == 31) { s_wq[warp] = qi; s_wr[warp] = rli; }
        float ar = attnAcc;
        #pragma unroll
        for (int o = 16; o > 0; o >>= 1) ar += __shfl_xor_sync(0xffffffffu, ar, o);
        if (lane == 0) s_red[warp] = ar;
        __syncthreads();
        if (tid == 0) {
            int qa = 0, ra = 0; float asum = 0.f;
            #pragma unroll
            for (int w = 0; w < 8; w++) {
                const int tq = s_wq[w]; s_wq[w] = qa; qa += tq;
                const int tr = s_wr[w]; s_wr[w] = ra; ra += tr;
                asum += s_red[w];
            }
            g_vid_attn[b] = asum / (float)max(total, 1);
            g_nqual[b]    = qa;
            s_nq = qa; s_trows = ra;
            const int nch8 = (qa + 7) >> 3;
            s_nch8  = nch8;
            s_ubase = nch8 ? atomicAdd(&g_ucount, nch8) : 0;
        }
        __syncthreads();
        int kb = s_wq[warp] + (qi - q);
        int rb = s_wr[warp] + (rli - rl);
        for (int i = 0; i < nloc; i++) {
            const int k  = kb + i;
            const int t0 = t0l[i], L = Ll[i];
            const float ic = icl[i], ir = irl[i];
            if ((k & 3) == 0) g_chunkoff[b * 258 + (k >> 2)] = rb;
            for (int l = 0; l < L; l++) {
                const int t = t0 + l;
                const int rep = (s_repW[t >> 5] >> (t & 31)) & 1;
                const float cf = ic - (rep ? ir : 0.f);
                const int tw = t | ((l == L - 1) ? (int)0x80000000 : 0);
                g_rows[(b << 11) + rb + l] = make_int2(tw, __float_as_int(cf));
            }
            rb += L;
        }
        {
            const int nq = s_nq, trows = s_trows;
            for (int idx = tid; idx < 257; idx += 256)
                if (4 * idx >= nq) g_chunkoff[b * 258 + idx] = trows;
            for (int c = tid; c < s_nch8; c += 256)
                g_units[s_ubase + c] = (b << 8) | c;
        }
        __threadfence();
        __syncthreads();
        if (tid == 0) atomicAdd(&g_ready, 1);
    }

    // ====================== phase 2: wait for all metadata ===================
    if (tid == 0) {
        while (atomicAdd(&g_ready, 0) < BV) __nanosleep(64);
        s_nunits = atomicAdd(&g_ucount, 0);
    }
    __syncthreads();
    __threadfence();
    const int nunits = s_nunits;

    // ====================== phase 3: work-stealing feat streaming ============
    const int grp = tid >> 7;          // group 0: runs [8c,8c+4), group 1: next 4
    const int cid = tid & 127;         // float4 column within D=512

    while (true) {
        if (tid == 0) s_u = atomicAdd(&g_qhead, 1);
        __syncthreads();
        const int u = s_u;
        if (u >= nunits) break;

        const int ue = __ldg(&g_units[u]);
        const int b  = ue >> 8;
        const int c  = ue & 255;
        const int* offp = g_chunkoff + b * 258 + 2 * c + grp;
        const int lo = __ldg(offp);
        const int hi = __ldg(offp + 1);
        const int2* rp = g_rows + (b << 11);
        const float4* fb = (const float4*)feat + ((size_t)(b << 11)) * 128 + cid;

        float4 acc = make_float4(0.f, 0.f, 0.f, 0.f);
        float ts = 0.f;
        for (int base = lo; base < hi; base += 4) {
            const int m = hi - base;
            int2 e0, e1, e2, e3;
            float4 f0, f1, f2, f3;
            e0 = __ldg(rp + base);
            f0 = __ldg(fb + (size_t)(e0.x & 0x7fffffff) * 128);
            if (m > 1) { e1 = __ldg(rp + base + 1); f1 = __ldg(fb + (size_t)(e1.x & 0x7fffffff) * 128); }
            if (m > 2) { e2 = __ldg(rp + base + 2); f2 = __ldg(fb + (size_t)(e2.x & 0x7fffffff) * 128); }
            if (m > 3) { e3 = __ldg(rp + base + 3); f3 = __ldg(fb + (size_t)(e3.x & 0x7fffffff) * 128); }

            float cf = __int_as_float(e0.y);
            acc.x += cf * f0.x; acc.y += cf * f0.y; acc.z += cf * f0.z; acc.w += cf * f0.w;
            if (e0.x < 0) { ts += acc.x*acc.x + acc.y*acc.y + acc.z*acc.z + acc.w*acc.w;
                            acc = make_float4(0.f, 0.f, 0.f, 0.f); }
            if (m > 1) {
                cf = __int_as_float(e1.y);
                acc.x += cf * f1.x; acc.y += cf * f1.y; acc.z += cf * f1.z; acc.w += cf * f1.w;
                if (e1.x < 0) { ts += acc.x*acc.x + acc.y*acc.y + acc.z*acc.z + acc.w*acc.w;
                                acc = make_float4(0.f, 0.f, 0.f, 0.f); }
            }
            if (m > 2) {
                cf = __int_as_float(e2.y);
                acc.x += cf * f2.x; acc.y += cf * f2.y; acc.z += cf * f2.z; acc.w += cf * f2.w;
                if (e2.x < 0) { ts += acc.x*acc.x + acc.y*acc.y + acc.z*acc.z + acc.w*acc.w;
                                acc = make_float4(0.f, 0.f, 0.f, 0.f); }
            }
            if (m > 3) {
                cf = __int_as_float(e3.y);
                acc.x += cf * f3.x; acc.y += cf * f3.y; acc.z += cf * f3.z; acc.w += cf * f3.w;
                if (e3.x < 0) { ts += acc.x*acc.x + acc.y*acc.y + acc.z*acc.z + acc.w*acc.w;
                                acc = make_float4(0.f, 0.f, 0.f, 0.f); }
            }
        }
        #pragma unroll
        for (int o = 16; o > 0; o >>= 1) ts += __shfl_xor_sync(0xffffffffu, ts, o);
        if (lane == 0) s_part[warp] = ts;
        __syncthreads();
        if (tid == 0) {
            float tot = 0.f;
            #pragma unroll
            for (int w = 0; w < 8; w++) tot += s_part[w];
            g_usum[b * 128 + c] = tot;        // fixed slot -> deterministic
        }
    }

    // ====================== phase 4: last block finalizes ====================
    if (tid == 0) {
        __threadfence();
        const int old = atomicAdd(&g_done, 1);
        s_isLast = (old == (int)gridDim.x - 1) ? 1 : 0;
    }
    __syncthreads();
    if (s_isLast) {
        __threadfence();
        float acc = 0.f;
        for (int j = tid; j < MAXU; j += 256) acc += g_usum[j];
        #pragma unroll
        for (int o = 16; o > 0; o >>= 1) acc += __shfl_xor_sync(0xffffffffu, acc, o);
        if (lane == 0) s_red[warp] = acc;
        __syncthreads();
        if (tid == 0) {
            float f = 0.f;
            #pragma unroll
            for (int w = 0; w < 8; w++) f += s_red[w];
            float asum = 0.f; int qs = 0;
            #pragma unroll
            for (int v = 0; v < BV; v++) { asum += g_vid_attn[v]; qs += g_nqual[v]; }
            const float feat_loss = (f * (1.0f / (float)DD)) / (float)max(qs, 1);
            const float attn_loss = asum / (float)BV;
            out[0] = feat_loss + attn_loss;   // FW = AW = 1
            g_qhead  = 0;                     // reset for next graph replay
            g_ucount = 0;
            g_ready  = 0;
            g_done   = 0;
        }
    }
}

// ============================================================================
extern "C" void kernel_launch(void* const* d_in, const int* in_sizes, int n_in,
                              void* d_out, int out_size)
{
    const float* attn = (const float*)d_in[0];
    const float* feat = (const float*)d_in[1];
    if (n_in >= 2 && in_sizes[0] > in_sizes[1]) {
        const float* tmp = attn; attn = feat; feat = tmp;
    }
    fusedKernel<<<GBLK, 256>>>(attn, feat, (float*)d_out);
}

// round 11
// speedup vs baseline: 1.1969x; 1.1969x over previous
#include <cuda_runtime.h>
#include <cstdint>

#define BV     32
#define TT     2048
#define DD     512
#define MAXRUN 1024
#define GBLK   608                  // 152 SMs * 4
#define NITEM  (BV * 1024)          // (video, 4-run group, quarter-D) items
#define CTf    0.7f
#define CPTf   0.5f

// ---------------- device scratch (no allocations allowed) ----------------
// g_meta[b*1024 + k], k < g_nqual[b]: {as_int start, as_int len, 1/cnt, 1/rep}
// Fixed slots, recomputed every launch from inputs -> deterministic; stale
// slots beyond nqual are never read.
__device__ float4 g_meta[BV * MAXRUN];
__device__ float  g_vid_attn[BV];
__device__ int    g_nqual[BV];
__device__ float  g_bsum[GBLK];

// ============================================================================
// Kernel A: bit-parallel run analysis, one block per video, no atomics.
// ============================================================================
__global__ __launch_bounds__(256) void runAnalysisKernel(const float* __restrict__ attn)
{
    __shared__ float         s_attn[TT];          // 8 KB
    __shared__ unsigned char s_predB[256];
    __shared__ unsigned int  s_word[64];
    __shared__ int           s_scnt[64];
    __shared__ int           s_wbase[64];
    __shared__ int           s_total;
    __shared__ int           s_rstart[MAXRUN];
    __shared__ int           s_rlen[MAXRUN];
    __shared__ float         s_rmse[MAXRUN];
    __shared__ float         s_ric[MAXRUN];
    __shared__ float         s_rir[MAXRUN];
    __shared__ int           s_wq[8];
    __shared__ float         s_red[8];

    const int b    = blockIdx.x;
    const int tid  = threadIdx.x;
    const int lane = tid & 31;
    const int warp = tid >> 5;
    const float* a_row = attn + (b << 11);

    const float4 v0 = ((const float4*)a_row)[tid * 2];
    const float4 v1 = ((const float4*)a_row)[tid * 2 + 1];
    ((float4*)s_attn)[tid * 2]     = v0;
    ((float4*)s_attn)[tid * 2 + 1] = v1;
    const float av[8] = {v0.x, v0.y, v0.z, v0.w, v1.x, v1.y, v1.z, v1.w};
    unsigned int pb = 0;
    #pragma unroll
    for (int j = 0; j < 8; j++) pb |= (av[j] > CPTf ? 1u : 0u) << j;
    s_predB[tid] = (unsigned char)pb;
    __syncthreads();

    unsigned int myStart = 0, myWord = 0;
    if (tid < 64) {
        myWord = (unsigned)s_predB[4*tid]
               | ((unsigned)s_predB[4*tid+1] << 8)
               | ((unsigned)s_predB[4*tid+2] << 16)
               | ((unsigned)s_predB[4*tid+3] << 24);
        const unsigned carry = tid ? ((s_predB[4*tid - 1] >> 7) & 1u) : 0u;
        myStart = myWord & ~((myWord << 1) | carry);
        s_word[tid] = myWord;
        s_scnt[tid] = __popc(myStart);
    }
    __syncthreads();

    if (warp == 0) {                       // scan 64 per-word start counts
        const int c0 = s_scnt[2*lane], c1 = s_scnt[2*lane+1];
        int incl = c0 + c1;
        #pragma unroll
        for (int o = 1; o < 32; o <<= 1) {
            int u = __shfl_up_sync(0xffffffffu, incl, o);
            if (lane >= o) incl += u;
        }
        const int excl = incl - (c0 + c1);
        s_wbase[2*lane]     = excl;
        s_wbase[2*lane + 1] = excl + c0;
        if (lane == 31) s_total = incl;
    }
    __syncthreads();

    // ---- run extraction + per-run stats (no atomics) ----
    if (tid < 64 && myStart) {
        int rbase = s_wbase[tid];
        unsigned sb = myStart;
        while (sb) {
            const int bit = __ffs(sb) - 1; sb &= sb - 1;
            const int t0 = tid * 32 + bit;
            int len = 0, ww = tid;
            unsigned cur = myWord >> bit;
            int avail = 32 - bit;
            while (true) {
                const unsigned inv = ~cur;
                int c = inv ? (__ffs(inv) - 1) : 32;
                if (c > avail) c = avail;
                len += c;
                if (c < avail) break;
                if (++ww >= 64) break;
                cur = s_word[ww]; avail = 32;
            }
            float sum = 0.f; int rep = 0;
            for (int j = 0; j < len; j++) {
                const float a = s_attn[t0 + j];
                sum += a; rep += (a > CTf) ? 1 : 0;
            }
            const float mean = sum / (float)len;
            float ssq = 0.f;
            for (int j = 0; j < len; j++) {
                const float d = s_attn[t0 + j] - mean;
                ssq += d * d;
            }
            s_rstart[rbase] = t0;
            s_rlen[rbase]   = len;
            s_rmse[rbase]   = ssq / (float)len;
            s_ric[rbase]    = 1.0f / (float)len;
            s_rir[rbase]    = (rep > 0) ? (1.0f / (float)rep) : 0.0f;
            rbase++;
        }
    }
    __syncthreads();

    // ---- compact qual runs into g_meta + attn-level reduction ----
    const int total = s_total;
    float attnAcc = 0.f;
    int q = 0;
    #pragma unroll
    for (int j = 0; j < 4; j++) {
        const int r = 4*tid + j;
        if (r < total) {
            attnAcc += s_rmse[r];
            q += (s_rir[r] != 0.f) ? 1 : 0;
        }
    }
    int qi = q;
    #pragma unroll
    for (int o = 1; o < 32; o <<= 1) {
        int u = __shfl_up_sync(0xffffffffu, qi, o);
        if (lane >= o) qi += u;
    }
    if (lane == 31) s_wq[warp] = qi;
    float ar = attnAcc;
    #pragma unroll
    for (int o = 16; o > 0; o >>= 1) ar += __shfl_xor_sync(0xffffffffu, ar, o);
    if (lane == 0) s_red[warp] = ar;
    __syncthreads();
    if (tid == 0) {
        int qa = 0; float asum = 0.f;
        #pragma unroll
        for (int w = 0; w < 8; w++) {
            const int tq = s_wq[w]; s_wq[w] = qa; qa += tq;
            asum += s_red[w];
        }
        g_vid_attn[b] = asum / (float)max(total, 1);
        g_nqual[b]    = qa;
    }
    __syncthreads();
    int base = s_wq[warp] + (qi - q);
    #pragma unroll
    for (int j = 0; j < 4; j++) {
        const int r = 4*tid + j;
        if (r < total && s_rir[r] != 0.f) {
            float4 m;
            m.x = __int_as_float(s_rstart[r]);
            m.y = __int_as_float(s_rlen[r]);
            m.z = s_ric[r];
            m.w = s_rir[r];
            g_meta[(b << 10) + base] = m;
            base++;
        }
    }
}

// ============================================================================
// Kernel B: one warp per (4-run group, quarter-D). 4 independent runs give
// 8 independent loads per loop iteration; accumulators are per-run (no
// cross-run dependency), squared only at run end.
// ============================================================================
__global__ __launch_bounds__(256) void featKernel(const float* __restrict__ attn,
                                                  const float* __restrict__ feat)
{
    __shared__ int   s_nq[BV];
    __shared__ float s_part[8];

    const int tid  = threadIdx.x;
    const int lane = tid & 31;
    const int warp = tid >> 5;
    if (tid < BV) s_nq[tid] = g_nqual[tid];
    __syncthreads();

    const int gw     = blockIdx.x * 8 + warp;
    const int stride = gridDim.x * 8;
    float ts = 0.f;

    for (int it = gw; it < NITEM; it += stride) {
        const int b    = it >> 10;
        const int rest = it & 1023;
        const int g    = rest >> 2;        // 4-run group
        const int qtr  = rest & 3;         // quarter of D (128 floats)
        const int k0   = g << 2;
        const int nq   = s_nq[b];
        if (k0 >= nq) continue;
        const int n = min(4, nq - k0);

        const float4* mp = g_meta + (b << 10) + k0;
        const float4 m0 = __ldg(mp);
        const float4 m1 = (n > 1) ? __ldg(mp + 1) : make_float4(0.f,0.f,0.f,0.f);
        const float4 m2 = (n > 2) ? __ldg(mp + 2) : make_float4(0.f,0.f,0.f,0.f);
        const float4 m3 = (n > 3) ? __ldg(mp + 3) : make_float4(0.f,0.f,0.f,0.f);

        const int s0 = __float_as_int(m0.x), L0 = __float_as_int(m0.y);
        const int s1 = __float_as_int(m1.x), L1 = (n > 1) ? __float_as_int(m1.y) : 0;
        const int s2 = __float_as_int(m2.x), L2 = (n > 2) ? __float_as_int(m2.y) : 0;
        const int s3 = __float_as_int(m3.x), L3 = (n > 3) ? __float_as_int(m3.y) : 0;

        const float* arow = attn + (b << 11);
        const float4* fb  = (const float4*)feat + ((size_t)(b << 11)) * 128
                          + (qtr << 5) + lane;

        float4 A0 = make_float4(0.f,0.f,0.f,0.f);
        float4 A1 = A0, A2 = A0, A3 = A0;

        int maxL = L0;
        maxL = max(maxL, L1); maxL = max(maxL, L2); maxL = max(maxL, L3);

        for (int j = 0; j < maxL; j++) {
            if (j < L0) {
                const float a = __ldg(arow + s0 + j);
                const float4 f = __ldg(fb + (size_t)(s0 + j) * 128);
                const float c = m0.z - ((a > CTf) ? m0.w : 0.f);
                A0.x += c*f.x; A0.y += c*f.y; A0.z += c*f.z; A0.w += c*f.w;
            }
            if (j < L1) {
                const float a = __ldg(arow + s1 + j);
                const float4 f = __ldg(fb + (size_t)(s1 + j) * 128);
                const float c = m1.z - ((a > CTf) ? m1.w : 0.f);
                A1.x += c*f.x; A1.y += c*f.y; A1.z += c*f.z; A1.w += c*f.w;
            }
            if (j < L2) {
                const float a = __ldg(arow + s2 + j);
                const float4 f = __ldg(fb + (size_t)(s2 + j) * 128);
                const float c = m2.z - ((a > CTf) ? m2.w : 0.f);
                A2.x += c*f.x; A2.y += c*f.y; A2.z += c*f.z; A2.w += c*f.w;
            }
            if (j < L3) {
                const float a = __ldg(arow + s3 + j);
                const float4 f = __ldg(fb + (size_t)(s3 + j) * 128);
                const float c = m3.z - ((a > CTf) ? m3.w : 0.f);
                A3.x += c*f.x; A3.y += c*f.y; A3.z += c*f.z; A3.w += c*f.w;
            }
        }

        ts += A0.x*A0.x + A0.y*A0.y + A0.z*A0.z + A0.w*A0.w
            + A1.x*A1.x + A1.y*A1.y + A1.z*A1.z + A1.w*A1.w
            + A2.x*A2.x + A2.y*A2.y + A2.z*A2.z + A2.w*A2.w
            + A3.x*A3.x + A3.y*A3.y + A3.z*A3.z + A3.w*A3.w;
    }

    #pragma unroll
    for (int o = 16; o > 0; o >>= 1) ts += __shfl_xor_sync(0xffffffffu, ts, o);
    if (lane == 0) s_part[warp] = ts;
    __syncthreads();
    if (tid == 0) {
        float tot = 0.f;
        #pragma unroll
        for (int w = 0; w < 8; w++) tot += s_part[w];
        g_bsum[blockIdx.x] = tot;          // fully rewritten every launch
    }
}

// ============================================================================
// Kernel C: final reduction -> scalar loss
// ============================================================================
__global__ __launch_bounds__(256) void finishKernel(float* __restrict__ out)
{
    __shared__ float s_f[256];
    const int tid = threadIdx.x;
    float acc = 0.f;
    for (int i = tid; i < GBLK; i += 256) acc += g_bsum[i];
    s_f[tid] = acc;
    __syncthreads();
    for (int off = 128; off > 0; off >>= 1) {
        if (tid < off) s_f[tid] += s_f[tid + off];
        __syncthreads();
    }
    if (tid == 0) {
        float asum = 0.f; int qs = 0;
        #pragma unroll
        for (int b = 0; b < BV; b++) { asum += g_vid_attn[b]; qs += g_nqual[b]; }
        const float feat_loss = (s_f[0] * (1.0f / (float)DD)) / (float)max(qs, 1);
        const float attn_loss = asum / (float)BV;
        out[0] = feat_loss + attn_loss;    // FW = AW = 1
    }
}

// ============================================================================
extern "C" void kernel_launch(void* const* d_in, const int* in_sizes, int n_in,
                              void* d_out, int out_size)
{
    const float* attn = (const float*)d_in[0];
    const float* feat = (const float*)d_in[1];
    if (n_in >= 2 && in_sizes[0] > in_sizes[1]) {
        const float* tmp = attn; attn = feat; feat = tmp;
    }

    runAnalysisKernel<<<BV, 256>>>(attn);
    featKernel<<<GBLK, 256>>>(attn, feat);
    finishKernel<<<1, 256>>>((float*)d_out);
}

// round 12
// speedup vs baseline: 1.6052x; 1.3411x over previous
#include <cuda_runtime.h>
#include <cstdint>

#define BV     32
#define TT     2048
#define DD     512
#define MAXRUN 1024
#define GBLK   608                  // 152 SMs * 4
#define NITEM  (BV * 1024)          // (video, 4-run group, quarter-D) items
#define CTf    0.7f
#define CPTf   0.5f

// ---------------- device scratch (no allocations allowed) ----------------
__device__ float4 g_meta[BV * MAXRUN];   // {start, len, 1/cnt, 1/rep}, compacted quals
__device__ float  g_vid_attn[BV];
__device__ int    g_nqual[BV];
__device__ float  g_bsum[GBLK];
__device__ int    g_done;                // reset by last block each launch

// ============================================================================
// Kernel A: run analysis. Start/end positions written without atomics
// (unique writer per run); stats computed run-parallel across all threads.
// ============================================================================
__global__ __launch_bounds__(256) void runAnalysisKernel(const float* __restrict__ attn)
{
    __shared__ float         s_attn[TT];          // 8 KB
    __shared__ unsigned char s_predB[258];        // [0] and [257] are sentinels
    __shared__ int           s_wTot[8];
    __shared__ int           s_total;
    __shared__ int           s_rstart[MAXRUN];
    __shared__ int           s_rend[MAXRUN];
    __shared__ int           s_wq[8];
    __shared__ float         s_red[8];

    const int b    = blockIdx.x;
    const int tid  = threadIdx.x;
    const int lane = tid & 31;
    const int warp = tid >> 5;
    const float* a_row = attn + (b << 11);

    const float4 v0 = ((const float4*)a_row)[tid * 2];
    const float4 v1 = ((const float4*)a_row)[tid * 2 + 1];
    ((float4*)s_attn)[tid * 2]     = v0;
    ((float4*)s_attn)[tid * 2 + 1] = v1;
    const float av[8] = {v0.x, v0.y, v0.z, v0.w, v1.x, v1.y, v1.z, v1.w};
    unsigned int pb = 0;
    #pragma unroll
    for (int j = 0; j < 8; j++) pb |= (av[j] > CPTf ? 1u : 0u) << j;
    s_predB[tid + 1] = (unsigned char)pb;
    if (tid == 0) { s_predB[0] = 0; s_predB[257] = 0; }
    __syncthreads();

    const unsigned prevB = s_predB[tid];
    const unsigned nextB = s_predB[tid + 2];
    const unsigned carry = (prevB >> 7) & 1u;            // pred at base_t-1
    const unsigned nxt   = (nextB & 1u) << 8;            // pred at base_t+8
    const unsigned ext   = pb | nxt;                     // 9-bit lookahead
    const unsigned stBits = pb & ~((pb << 1) | carry);   // run starts
    const unsigned enBits = pb & ~(ext >> 1);            // run ends

    // per-thread inclusive prefix of start counts
    int pref[8];
    int localTot = 0;
    #pragma unroll
    for (int j = 0; j < 8; j++) {
        localTot += (stBits >> j) & 1;
        pref[j] = localTot;
    }
    int incl = localTot;
    #pragma unroll
    for (int o = 1; o < 32; o <<= 1) {
        int u = __shfl_up_sync(0xffffffffu, incl, o);
        if (lane >= o) incl += u;
    }
    if (lane == 31) s_wTot[warp] = incl;
    __syncthreads();
    if (tid == 0) {
        int acc = 0;
        #pragma unroll
        for (int w = 0; w < 8; w++) { const int v = s_wTot[w]; s_wTot[w] = acc; acc += v; }
        s_total = acc;
    }
    __syncthreads();

    const int threadBase = s_wTot[warp] + (incl - localTot);
    const int base_t = tid * 8;
    #pragma unroll
    for (int j = 0; j < 8; j++) {
        const int rid = threadBase + pref[j] - 1;        // valid where pred
        if ((stBits >> j) & 1) s_rstart[rid] = base_t + j;
        if ((enBits >> j) & 1) s_rend[rid]   = base_t + j;
    }
    __syncthreads();

    // ---- run-parallel stats: 4 contiguous runs per thread ----
    const int total = s_total;
    float attnAcc = 0.f;
    int   t0l[4], lenl[4];
    float irl[4];
    int   q = 0;
    #pragma unroll
    for (int j = 0; j < 4; j++) {
        const int r = 4 * tid + j;
        t0l[j] = 0; lenl[j] = 0; irl[j] = 0.f;
        if (r < total) {
            const int t0  = s_rstart[r];
            const int len = s_rend[r] - t0 + 1;
            float sum = 0.f; int rep = 0;
            for (int l = 0; l < len; l++) {
                const float a = s_attn[t0 + l];
                sum += a; rep += (a > CTf) ? 1 : 0;
            }
            const float mean = sum / (float)len;
            float ssq = 0.f;
            for (int l = 0; l < len; l++) {
                const float d = s_attn[t0 + l] - mean;
                ssq += d * d;
            }
            attnAcc += ssq / (float)len;
            t0l[j]  = t0;
            lenl[j] = len;
            irl[j]  = (rep > 0) ? (1.0f / (float)rep) : 0.0f;
            q += (rep > 0) ? 1 : 0;
        }
    }

    // ---- compaction scan for qualifying runs + attn reduction ----
    int qi = q;
    #pragma unroll
    for (int o = 1; o < 32; o <<= 1) {
        int u = __shfl_up_sync(0xffffffffu, qi, o);
        if (lane >= o) qi += u;
    }
    if (lane == 31) s_wq[warp] = qi;
    float ar = attnAcc;
    #pragma unroll
    for (int o = 16; o > 0; o >>= 1) ar += __shfl_xor_sync(0xffffffffu, ar, o);
    if (lane == 0) s_red[warp] = ar;
    __syncthreads();
    if (tid == 0) {
        int qa = 0; float asum = 0.f;
        #pragma unroll
        for (int w = 0; w < 8; w++) {
            const int tq = s_wq[w]; s_wq[w] = qa; qa += tq;
            asum += s_red[w];
        }
        g_vid_attn[b] = asum / (float)max(total, 1);
        g_nqual[b]    = qa;
    }
    __syncthreads();
    int slot = s_wq[warp] + (qi - q);
    #pragma unroll
    for (int j = 0; j < 4; j++) {
        if (irl[j] != 0.f) {
            float4 m;
            m.x = __int_as_float(t0l[j]);
            m.y = __int_as_float(lenl[j]);
            m.z = 1.0f / (float)lenl[j];
            m.w = irl[j];
            g_meta[(b << 10) + slot] = m;
            slot++;
        }
    }
}

// ============================================================================
// Kernel B: one warp per (4-run group, quarter-D); 8 independent loads per
// iteration, per-run accumulators; last-done block finalizes the scalar loss.
// ============================================================================
__global__ __launch_bounds__(256) void featKernel(const float* __restrict__ attn,
                                                  const float* __restrict__ feat,
                                                  float* __restrict__ out)
{
    __shared__ int   s_nq[BV];
    __shared__ float s_part[8];
    __shared__ float s_red[8];
    __shared__ int   s_isLast;

    const int tid  = threadIdx.x;
    const int lane = tid & 31;
    const int warp = tid >> 5;
    if (tid < BV) s_nq[tid] = g_nqual[tid];
    __syncthreads();

    const int gw     = blockIdx.x * 8 + warp;
    const int stride = gridDim.x * 8;
    float ts = 0.f;

    for (int it = gw; it < NITEM; it += stride) {
        const int b    = it >> 10;
        const int rest = it & 1023;
        const int g    = rest >> 2;        // 4-run group
        const int qtr  = rest & 3;         // quarter of D (128 floats)
        const int k0   = g << 2;
        const int nq   = s_nq[b];
        if (k0 >= nq) continue;
        const int n = min(4, nq - k0);

        const float4* mp = g_meta + (b << 10) + k0;
        const float4 m0 = __ldg(mp);
        const float4 m1 = (n > 1) ? __ldg(mp + 1) : make_float4(0.f,0.f,0.f,0.f);
        const float4 m2 = (n > 2) ? __ldg(mp + 2) : make_float4(0.f,0.f,0.f,0.f);
        const float4 m3 = (n > 3) ? __ldg(mp + 3) : make_float4(0.f,0.f,0.f,0.f);

        const int s0 = __float_as_int(m0.x), L0 = __float_as_int(m0.y);
        const int s1 = __float_as_int(m1.x), L1 = (n > 1) ? __float_as_int(m1.y) : 0;
        const int s2 = __float_as_int(m2.x), L2 = (n > 2) ? __float_as_int(m2.y) : 0;
        const int s3 = __float_as_int(m3.x), L3 = (n > 3) ? __float_as_int(m3.y) : 0;

        const float* arow = attn + (b << 11);
        const float4* fb  = (const float4*)feat + ((size_t)(b << 11)) * 128
                          + (qtr << 5) + lane;

        float4 A0 = make_float4(0.f,0.f,0.f,0.f);
        float4 A1 = A0, A2 = A0, A3 = A0;

        int maxL = L0;
        maxL = max(maxL, L1); maxL = max(maxL, L2); maxL = max(maxL, L3);

        for (int j = 0; j < maxL; j++) {
            if (j < L0) {
                const float a = __ldg(arow + s0 + j);
                const float4 f = __ldg(fb + (size_t)(s0 + j) * 128);
                const float c = m0.z - ((a > CTf) ? m0.w : 0.f);
                A0.x += c*f.x; A0.y += c*f.y; A0.z += c*f.z; A0.w += c*f.w;
            }
            if (j < L1) {
                const float a = __ldg(arow + s1 + j);
                const float4 f = __ldg(fb + (size_t)(s1 + j) * 128);
                const float c = m1.z - ((a > CTf) ? m1.w : 0.f);
                A1.x += c*f.x; A1.y += c*f.y; A1.z += c*f.z; A1.w += c*f.w;
            }
            if (j < L2) {
                const float a = __ldg(arow + s2 + j);
                const float4 f = __ldg(fb + (size_t)(s2 + j) * 128);
                const float c = m2.z - ((a > CTf) ? m2.w : 0.f);
                A2.x += c*f.x; A2.y += c*f.y; A2.z += c*f.z; A2.w += c*f.w;
            }
            if (j < L3) {
                const float a = __ldg(arow + s3 + j);
                const float4 f = __ldg(fb + (size_t)(s3 + j) * 128);
                const float c = m3.z - ((a > CTf) ? m3.w : 0.f);
                A3.x += c*f.x; A3.y += c*f.y; A3.z += c*f.z; A3.w += c*f.w;
            }
        }

        ts += A0.x*A0.x + A0.y*A0.y + A0.z*A0.z + A0.w*A0.w
            + A1.x*A1.x + A1.y*A1.y + A1.z*A1.z + A1.w*A1.w
            + A2.x*A2.x + A2.y*A2.y + A2.z*A2.z + A2.w*A2.w
            + A3.x*A3.x + A3.y*A3.y + A3.z*A3.z + A3.w*A3.w;
    }

    #pragma unroll
    for (int o = 16; o > 0; o >>= 1) ts += __shfl_xor_sync(0xffffffffu, ts, o);
    if (lane == 0) s_part[warp] = ts;
    __syncthreads();
    if (tid == 0) {
        float tot = 0.f;
        #pragma unroll
        for (int w = 0; w < 8; w++) tot += s_part[w];
        g_bsum[blockIdx.x] = tot;
        __threadfence();
        const int old = atomicAdd(&g_done, 1);
        s_isLast = (old == (int)gridDim.x - 1) ? 1 : 0;
    }
    __syncthreads();

    // ---- last-done block finalizes ----
    if (s_isLast) {
        __threadfence();
        float acc = 0.f;
        for (int i = tid; i < GBLK; i += 256) acc += g_bsum[i];
        #pragma unroll
        for (int o = 16; o > 0; o >>= 1) acc += __shfl_xor_sync(0xffffffffu, acc, o);
        if (lane == 0) s_red[warp] = acc;
        __syncthreads();
        if (tid == 0) {
            float f = 0.f;
            #pragma unroll
            for (int w = 0; w < 8; w++) f += s_red[w];
            float asum = 0.f; int qs = 0;
            #pragma unroll
            for (int v = 0; v < BV; v++) { asum += g_vid_attn[v]; qs += g_nqual[v]; }
            const float feat_loss = (f * (1.0f / (float)DD)) / (float)max(qs, 1);
            const float attn_loss = asum / (float)BV;
            out[0] = feat_loss + attn_loss;   // FW = AW = 1
            g_done = 0;                       // reset for next graph replay
        }
    }
}

// ============================================================================
extern "C" void kernel_launch(void* const* d_in, const int* in_sizes, int n_in,
                              void* d_out, int out_size)
{
    const float* attn = (const float*)d_in[0];
    const float* feat = (const float*)d_in[1];
    if (n_in >= 2 && in_sizes[0] > in_sizes[1]) {
        const float* tmp = attn; attn = feat; feat = tmp;
    }

    runAnalysisKernel<<<BV, 256>>>(attn);
    featKernel<<<GBLK, 256>>>(attn, feat, (float*)d_out);
}